// round 3
// baseline (speedup 1.0000x reference)
#include <cuda_runtime.h>
#include <cuda_bf16.h>
#include <cstdint>
#include <cstring>

__device__ float g_att[32 * 32];
__device__ float g_Sp[32 * 2048];
__device__ float g_cntp[32 * 32];
__device__ float g_rout[2048];
__device__ __nv_bfloat16 g_w1t[128 * 64];
__device__ __nv_bfloat16 g_w2t[64 * 128];

__device__ __forceinline__ float gelu_exact(float x) {
    return 0.5f * x * (1.0f + erff(x * 0.7071067811865476f));
}

__device__ __forceinline__ void mma16816(float (&c)[4],
    uint32_t a0, uint32_t a1, uint32_t a2, uint32_t a3, uint32_t b0, uint32_t b1) {
    asm volatile(
        "mma.sync.aligned.m16n8k16.row.col.f32.bf16.bf16.f32 "
        "{%0,%1,%2,%3}, {%4,%5,%6,%7}, {%8,%9}, {%0,%1,%2,%3};"
        : "+f"(c[0]), "+f"(c[1]), "+f"(c[2]), "+f"(c[3])
        : "r"(a0), "r"(a1), "r"(a2), "r"(a3), "r"(b0), "r"(b1));
}

// ---------- prep: zero scratch + transpose weights to bf16 ----------
__global__ void prep0_kernel(const float* __restrict__ vw1, const float* __restrict__ vw2) {
    int idx = blockIdx.x * blockDim.x + threadIdx.x;  // 16384 threads
    for (int o = idx; o < 32 * 2048; o += 16384) g_Sp[o] = 0.f;
    if (idx < 32 * 32) g_cntp[idx] = 0.f;
    if (idx < 8192) {
        g_w1t[idx] = __float2bfloat16(vw1[(idx & 63) * 128 + (idx >> 6)]);
        g_w2t[idx] = __float2bfloat16(vw2[(idx & 127) * 64 + (idx >> 7)]);
    }
}

// ---------- exact fp32 attention table ----------
__device__ __forceinline__ float blk_sum256(float v, float* sred, int t) {
    #pragma unroll
    for (int o = 16; o; o >>= 1) v += __shfl_xor_sync(0xffffffffu, v, o);
    __syncthreads();
    if ((t & 31) == 0) sred[t >> 5] = v;
    __syncthreads();
    float r = 0.f;
    #pragma unroll
    for (int w = 0; w < 8; w++) r += sred[w];
    return r;
}

__global__ void att_kernel(const float* __restrict__ qw1, const float* __restrict__ qb1,
                           const float* __restrict__ qg1, const float* __restrict__ qbt1,
                           const float* __restrict__ qw2, const float* __restrict__ qb2,
                           const float* __restrict__ qg2, const float* __restrict__ qbt2,
                           const float* __restrict__ qw3, const float* __restrict__ qb3,
                           const float* __restrict__ keys, const float* __restrict__ temperature) {
    __shared__ float sh[256], sq[256], sred[8], ssim[32];
    int t = threadIdx.x, idx = blockIdx.x;
    float v = 0.f;
    if (t < 128) {
        v = qb1[t];
        #pragma unroll
        for (int j = 0; j < 5; j++) v += (float)((idx >> j) & 1) * qw1[j * 128 + t];
    }
    float s1 = blk_sum256(v, sred, t);
    float s2 = blk_sum256(v * v, sred, t);
    if (t < 128) {
        float mean = s1 * (1.f / 128.f), var = s2 * (1.f / 128.f) - mean * mean;
        sh[t] = gelu_exact((v - mean) * rsqrtf(var + 1e-5f) * qg1[t] + qbt1[t]);
    }
    __syncthreads();
    float v2 = qb2[t];
    for (int k = 0; k < 128; k++) v2 += sh[k] * qw2[k * 256 + t];
    float s3 = blk_sum256(v2, sred, t);
    float s4 = blk_sum256(v2 * v2, sred, t);
    {
        float mean = s3 * (1.f / 256.f), var = s4 * (1.f / 256.f) - mean * mean;
        sh[t] = gelu_exact((v2 - mean) * rsqrtf(var + 1e-5f) * qg2[t] + qbt2[t]);
    }
    __syncthreads();
    float v3 = qb3[t];
    for (int k = 0; k < 256; k++) v3 += sh[k] * qw3[k * 256 + t];
    sq[t] = v3;
    float s5 = blk_sum256(v3 * v3, sred, t);
    float qnorm = fmaxf(sqrtf(s5), 1e-12f);
    int w = t >> 5, lane = t & 31;
    #pragma unroll
    for (int s = 0; s < 4; s++) {
        int n = w * 4 + s;
        float dot = 0.f, kn = 0.f;
        for (int d = lane; d < 256; d += 32) {
            float kv = keys[n * 256 + d];
            dot += sq[d] * kv; kn += kv * kv;
        }
        #pragma unroll
        for (int o = 16; o; o >>= 1) {
            dot += __shfl_xor_sync(0xffffffffu, dot, o);
            kn  += __shfl_xor_sync(0xffffffffu, kn, o);
        }
        if (lane == 0) ssim[n] = dot / (qnorm * fmaxf(sqrtf(kn), 1e-12f));
    }
    __syncthreads();
    if (t < 32) {
        float temp = fmaxf(fabsf(temperature[0]), 0.01f);
        float l = ssim[t] / temp, m = l;
        #pragma unroll
        for (int o = 16; o; o >>= 1) m = fmaxf(m, __shfl_xor_sync(0xffffffffu, m, o));
        float e = expf(l - m), ssum = e;
        #pragma unroll
        for (int o = 16; o; o >>= 1) ssum += __shfl_xor_sync(0xffffffffu, ssum, o);
        g_att[idx * 32 + t] = e / ssum;
    }
}

// ---------- enc: per-128-row tile, bf16 MMA MLP + one-hot scatter MMA ----------
#define ENC_SMEM_BYTES 56704
__global__ void __launch_bounds__(256) enc_kernel(
    const float* __restrict__ wval, const int* __restrict__ widx,
    const float* __restrict__ vb1, const float* __restrict__ vg1,
    const float* __restrict__ vbt1, const float* __restrict__ vb2) {
    extern __shared__ char smem[];
    uint32_t* sXu = (uint32_t*)(smem);                 // X bf16 [128][72] (stride 36 u32)
    __nv_bfloat16* sEt = (__nv_bfloat16*)(smem);       // reuse: E^T bf16 [64][136]
    uint32_t* sEtu = (uint32_t*)(smem);
    uint32_t* sW1u = (uint32_t*)(smem + 18432);        // W1^T [128][36 u32]
    uint32_t* sW2u = (uint32_t*)(smem + 36864);        // W2^T [64][68 u32]
    float* sSpart = (float*)(smem + 18432);            // reuse: [4][32][65] f32
    float* sVb1 = (float*)(smem + 54272);
    float* sVg1 = sVb1 + 128; float* sVbt1 = sVg1 + 128; float* sVb2 = sVbt1 + 128;
    int* sWidx = (int*)(smem + 56064);
    int* sCnt  = (int*)(smem + 56576);

    int tid = threadIdx.x, bid = blockIdx.x, rowbase = bid * 128;
    if (tid < 32) sCnt[tid] = 0;
    if (tid < 128) {
        sWidx[tid] = widx[rowbase + tid];
        sVb1[tid] = vb1[tid]; sVg1[tid] = vg1[tid]; sVbt1[tid] = vbt1[tid];
    }
    if (tid < 64) sVb2[tid] = vb2[tid];
    __syncthreads();
    if (tid < 128) atomicAdd(&sCnt[sWidx[tid]], 1);
    {
        const float2* wv2 = (const float2*)wval;
        #pragma unroll
        for (int rep = 0; rep < 16; rep++) {
            int o = rep * 256 + tid, r = o >> 5, cc = o & 31;
            float2 v = wv2[(size_t)(rowbase + r) * 32 + cc];
            if (sWidx[r] == 31) { v.x = 0.f; v.y = 0.f; }
            __nv_bfloat162 h = __floats2bfloat162_rn(v.x, v.y);
            uint32_t hu; memcpy(&hu, &h, 4);
            sXu[r * 36 + cc] = hu;
        }
        const uint32_t* w1 = (const uint32_t*)g_w1t;
        #pragma unroll
        for (int rep = 0; rep < 16; rep++) {
            int o = rep * 256 + tid;
            sW1u[(o >> 5) * 36 + (o & 31)] = w1[o];
        }
        const uint32_t* w2 = (const uint32_t*)g_w2t;
        #pragma unroll
        for (int rep = 0; rep < 16; rep++) {
            int o = rep * 256 + tid;
            sW2u[(o >> 6) * 68 + (o & 63)] = w2[o];
        }
    }
    __syncthreads();

    int w = tid >> 5, lane = tid & 31, g = lane >> 2, i = lane & 3;
    int r0 = w * 16 + g;

    // layer 1: X[128x64] @ W1[64x128]
    uint32_t A1[4][4];
    #pragma unroll
    for (int ks = 0; ks < 4; ks++) {
        int base = ks * 8 + i;
        A1[ks][0] = sXu[r0 * 36 + base];
        A1[ks][1] = sXu[(r0 + 8) * 36 + base];
        A1[ks][2] = sXu[r0 * 36 + base + 4];
        A1[ks][3] = sXu[(r0 + 8) * 36 + base + 4];
    }
    float C1[16][4];
    #pragma unroll
    for (int j = 0; j < 16; j++) C1[j][0] = C1[j][1] = C1[j][2] = C1[j][3] = 0.f;
    #pragma unroll
    for (int j = 0; j < 16; j++) {
        int nrow = j * 8 + g;
        #pragma unroll
        for (int ks = 0; ks < 4; ks++)
            mma16816(C1[j], A1[ks][0], A1[ks][1], A1[ks][2], A1[ks][3],
                     sW1u[nrow * 36 + ks * 8 + i], sW1u[nrow * 36 + ks * 8 + i + 4]);
    }
    // bias + LN stats + GELU, repack as layer-2 A fragments (in registers)
    #pragma unroll
    for (int j = 0; j < 16; j++) {
        float2 bb = *(float2*)&sVb1[j * 8 + i * 2];
        C1[j][0] += bb.x; C1[j][1] += bb.y; C1[j][2] += bb.x; C1[j][3] += bb.y;
    }
    float sum0 = 0.f, sq0 = 0.f, sum1 = 0.f, sq1 = 0.f;
    #pragma unroll
    for (int j = 0; j < 16; j++) {
        sum0 += C1[j][0] + C1[j][1]; sq0 += C1[j][0]*C1[j][0] + C1[j][1]*C1[j][1];
        sum1 += C1[j][2] + C1[j][3]; sq1 += C1[j][2]*C1[j][2] + C1[j][3]*C1[j][3];
    }
    #pragma unroll
    for (int o = 1; o <= 2; o <<= 1) {
        sum0 += __shfl_xor_sync(0xffffffffu, sum0, o);
        sq0  += __shfl_xor_sync(0xffffffffu, sq0, o);
        sum1 += __shfl_xor_sync(0xffffffffu, sum1, o);
        sq1  += __shfl_xor_sync(0xffffffffu, sq1, o);
    }
    float mean0 = sum0 * (1.f/128.f), var0 = sq0 * (1.f/128.f) - mean0*mean0;
    float mean1 = sum1 * (1.f/128.f), var1 = sq1 * (1.f/128.f) - mean1*mean1;
    float rs0 = rsqrtf(var0 + 1e-5f), rs1 = rsqrtf(var1 + 1e-5f);
    uint32_t A2[8][4];
    #pragma unroll
    for (int j = 0; j < 16; j++) {
        int c0 = j * 8 + i * 2;
        float2 gg = *(float2*)&sVg1[c0];
        float2 bb = *(float2*)&sVbt1[c0];
        float x0 = gelu_exact((C1[j][0] - mean0) * rs0 * gg.x + bb.x);
        float x1 = gelu_exact((C1[j][1] - mean0) * rs0 * gg.y + bb.y);
        float x2 = gelu_exact((C1[j][2] - mean1) * rs1 * gg.x + bb.x);
        float x3 = gelu_exact((C1[j][3] - mean1) * rs1 * gg.y + bb.y);
        __nv_bfloat162 p0 = __floats2bfloat162_rn(x0, x1);
        __nv_bfloat162 p1 = __floats2bfloat162_rn(x2, x3);
        uint32_t u0, u1; memcpy(&u0, &p0, 4); memcpy(&u1, &p1, 4);
        A2[j >> 1][(j & 1) * 2 + 0] = u0;
        A2[j >> 1][(j & 1) * 2 + 1] = u1;
    }
    // layer 2: H[128x128] @ W2[128x64]
    float C2[8][4];
    #pragma unroll
    for (int j = 0; j < 8; j++) C2[j][0] = C2[j][1] = C2[j][2] = C2[j][3] = 0.f;
    #pragma unroll
    for (int j = 0; j < 8; j++) {
        int nrow = j * 8 + g;
        #pragma unroll
        for (int ks = 0; ks < 8; ks++)
            mma16816(C2[j], A2[ks][0], A2[ks][1], A2[ks][2], A2[ks][3],
                     sW2u[nrow * 68 + ks * 8 + i], sW2u[nrow * 68 + ks * 8 + i + 4]);
    }
    #pragma unroll
    for (int j = 0; j < 8; j++) {
        float2 bb = *(float2*)&sVb2[j * 8 + i * 2];
        C2[j][0] += bb.x; C2[j][1] += bb.y; C2[j][2] += bb.x; C2[j][3] += bb.y;
    }
    __syncthreads();
    // store E^T bf16 [64][136], zero Spart
    #pragma unroll
    for (int j = 0; j < 8; j++) {
        int c0 = j * 8 + i * 2;
        sEt[(c0    ) * 136 + r0    ] = __float2bfloat16(C2[j][0]);
        sEt[(c0 + 1) * 136 + r0    ] = __float2bfloat16(C2[j][1]);
        sEt[(c0    ) * 136 + r0 + 8] = __float2bfloat16(C2[j][2]);
        sEt[(c0 + 1) * 136 + r0 + 8] = __float2bfloat16(C2[j][3]);
    }
    #pragma unroll
    for (int rep = 0; rep < 33; rep++) {
        int o = rep * 256 + tid;
        if (o < 4 * 32 * 65) sSpart[o] = 0.f;
    }
    __syncthreads();
    // S = Onehot(widx)^T (32x128) @ E (128x64); k-split across warp pairs
    int ksp = w >> 1, mh = w & 1;
    float CS[8][4];
    #pragma unroll
    for (int j = 0; j < 8; j++) CS[j][0] = CS[j][1] = CS[j][2] = CS[j][3] = 0.f;
    #pragma unroll
    for (int ks2 = 0; ks2 < 2; ks2++) {
        int kb = ksp * 32 + ks2 * 16, k0 = kb + i * 2;
        int x0 = sWidx[k0], x1 = sWidx[k0 + 1], x2 = sWidx[k0 + 8], x3 = sWidx[k0 + 9];
        int mlo = mh * 16 + g, mhi = mlo + 8;
        uint32_t a0 = (x0 == mlo ? 0x3F80u : 0u) | (x1 == mlo ? 0x3F800000u : 0u);
        uint32_t a1 = (x0 == mhi ? 0x3F80u : 0u) | (x1 == mhi ? 0x3F800000u : 0u);
        uint32_t a2 = (x2 == mlo ? 0x3F80u : 0u) | (x3 == mlo ? 0x3F800000u : 0u);
        uint32_t a3 = (x2 == mhi ? 0x3F80u : 0u) | (x3 == mhi ? 0x3F800000u : 0u);
        #pragma unroll
        for (int j = 0; j < 8; j++) {
            int nrow = j * 8 + g;
            mma16816(CS[j], a0, a1, a2, a3,
                     sEtu[nrow * 68 + (kb >> 1) + i], sEtu[nrow * 68 + (kb >> 1) + i + 4]);
        }
    }
    {
        float* p = &sSpart[ksp * 2080];
        int m0 = mh * 16 + g;
        #pragma unroll
        for (int j = 0; j < 8; j++) {
            int c0 = j * 8 + i * 2;
            p[m0 * 65 + c0]           = CS[j][0];
            p[m0 * 65 + c0 + 1]       = CS[j][1];
            p[(m0 + 8) * 65 + c0]     = CS[j][2];
            p[(m0 + 8) * 65 + c0 + 1] = CS[j][3];
        }
    }
    __syncthreads();
    int slice = bid & 31;
    #pragma unroll
    for (int rep = 0; rep < 8; rep++) {
        int o = rep * 256 + tid, m = o >> 6, c = o & 63;
        float v = sSpart[m * 65 + c] + sSpart[2080 + m * 65 + c]
                + sSpart[4160 + m * 65 + c] + sSpart[6240 + m * 65 + c];
        atomicAdd(&g_Sp[slice * 2048 + o], v);
    }
    if (tid < 32) atomicAdd(&g_cntp[slice * 32 + tid], (float)sCnt[tid]);
}

// ---------- finalize: new_regs + ROUT ----------
__global__ void finalize_kernel(const float* __restrict__ regvals,
                                const float* __restrict__ wstrength,
                                float* __restrict__ out, int Btot) {
    __shared__ float sS[2048], sATT[1024], sCnt[32], sM[32], sNR[2048];
    int t = threadIdx.x;  // 1024
    sATT[t] = g_att[t];
    #pragma unroll
    for (int rep = 0; rep < 2; rep++) {
        int o = rep * 1024 + t;
        float v = 0.f;
        for (int sl = 0; sl < 32; sl++) v += g_Sp[sl * 2048 + o];
        sS[o] = v;
    }
    if (t < 32) {
        float c = 0.f;
        for (int sl = 0; sl < 32; sl++) c += g_cntp[sl * 32 + t];
        sCnt[t] = c;
    }
    __syncthreads();
    float invB = 1.f / (float)Btot;
    if (t < 32) {
        float m = 0.f;
        for (int i2 = 0; i2 < 32; i2++) m += sCnt[i2] * invB * sATT[i2 * 32 + t];
        sM[t] = m;
    }
    __syncthreads();
    float s = 1.f / (1.f + expf(-wstrength[0]));
    #pragma unroll
    for (int rep = 0; rep < 2; rep++) {
        int o = rep * 1024 + t, n = o >> 6, d = o & 63;
        float as = 0.f;
        for (int i2 = 0; i2 < 32; i2++) as += sATT[i2 * 32 + n] * sS[i2 * 64 + d];
        float nr = (1.f - s * sM[n]) * regvals[o] + (s * invB) * as;
        out[(size_t)Btot * 64 + o] = nr;
        sNR[o] = nr;
    }
    __syncthreads();
    #pragma unroll
    for (int rep = 0; rep < 2; rep++) {
        int o = rep * 1024 + t, i2 = o >> 6, d = o & 63;
        float r = 0.f;
        for (int n = 0; n < 32; n++) r += sATT[i2 * 32 + n] * sNR[n * 64 + d];
        g_rout[o] = r;
    }
}

// ---------- read gather ----------
__global__ void __launch_bounds__(256) read_kernel(const int* __restrict__ ridx,
                                                   float* __restrict__ out) {
    __shared__ float4 sr[512];
    int t = threadIdx.x;
    #pragma unroll
    for (int rep = 0; rep < 2; rep++)
        sr[rep * 256 + t] = ((const float4*)g_rout)[rep * 256 + t];
    __syncthreads();
    int base = blockIdx.x * 128;
    #pragma unroll
    for (int it = 0; it < 8; it++) {
        int r = base + it * 16 + (t >> 4), cg = t & 15;
        int rv = ridx[r];
        float4 v = (rv == 31) ? make_float4(0.f, 0.f, 0.f, 0.f) : sr[rv * 16 + cg];
        ((float4*)out)[(size_t)r * 16 + cg] = v;
    }
}

// ---------- launcher ----------
extern "C" void kernel_launch(void* const* d_in, const int* in_sizes, int n_in,
                              void* d_out, int out_size) {
    const int*   wix  = (const int*)d_in[0];
    const float* wval = (const float*)d_in[1];
    const int*   rix  = (const int*)d_in[2];
    const float* regv = (const float*)d_in[3];
    const float* keys = (const float*)d_in[4];
    const float* qw1  = (const float*)d_in[5];
    const float* qb1  = (const float*)d_in[6];
    const float* qg1  = (const float*)d_in[7];
    const float* qbt1 = (const float*)d_in[8];
    const float* qw2  = (const float*)d_in[9];
    const float* qb2  = (const float*)d_in[10];
    const float* qg2  = (const float*)d_in[11];
    const float* qbt2 = (const float*)d_in[12];
    const float* qw3  = (const float*)d_in[13];
    const float* qb3  = (const float*)d_in[14];
    const float* vw1  = (const float*)d_in[15];
    const float* vb1  = (const float*)d_in[16];
    const float* vg1  = (const float*)d_in[17];
    const float* vbt1 = (const float*)d_in[18];
    const float* vw2  = (const float*)d_in[19];
    const float* vb2  = (const float*)d_in[20];
    const float* temp = (const float*)d_in[21];
    const float* wstr = (const float*)d_in[22];
    int B = in_sizes[0];

    cudaFuncSetAttribute(enc_kernel, cudaFuncAttributeMaxDynamicSharedMemorySize, ENC_SMEM_BYTES);

    prep0_kernel<<<64, 256>>>(vw1, vw2);
    att_kernel<<<32, 256>>>(qw1, qb1, qg1, qbt1, qw2, qb2, qg2, qbt2, qw3, qb3, keys, temp);
    enc_kernel<<<B / 128, 256, ENC_SMEM_BYTES>>>(wval, wix, vb1, vg1, vbt1, vb2);
    finalize_kernel<<<1, 1024>>>(regv, wstr, (float*)d_out, B);
    read_kernel<<<B / 128, 256>>>(rix, (float*)d_out);
}

// round 4
// speedup vs baseline: 1.0460x; 1.0460x over previous
#include <cuda_runtime.h>
#include <cuda_bf16.h>
#include <cstdint>
#include <cstring>

__device__ float g_att[32 * 32];
__device__ float g_Sp[32 * 2048];
__device__ float g_cntp[32 * 32];
__device__ float g_S[2048];
__device__ float g_cnt[32];
__device__ float g_rout[2048];
__device__ __nv_bfloat16 g_w1t[128 * 64];
__device__ __nv_bfloat16 g_w2t[64 * 128];

__device__ __forceinline__ float gelu_exact(float x) {
    return 0.5f * x * (1.0f + erff(x * 0.7071067811865476f));
}

// Fast exact-erf GELU: A&S 7.1.26, |erf err| <= 1.5e-7.  ~12 fma + 2 MUFU.
__device__ __forceinline__ float ex2_approx(float x) {
    float r; asm("ex2.approx.f32 %0, %1;" : "=f"(r) : "f"(x)); return r;
}
__device__ __forceinline__ float rcp_approx(float x) {
    float r; asm("rcp.approx.f32 %0, %1;" : "=f"(r) : "f"(x)); return r;
}
__device__ __forceinline__ float gelu_fast(float x) {
    float y = fabsf(x) * 0.7071067811865476f;
    float t = rcp_approx(fmaf(0.3275911f, y, 1.0f));
    float p = fmaf(t, fmaf(t, fmaf(t, fmaf(t, 1.061405429f, -1.453152027f),
                                   1.421413741f), -0.284496736f), 0.254829592f);
    float e = ex2_approx(y * y * -1.4426950408889634f);
    float erf_y = fmaf(-p * t, e, 1.0f);
    float s = copysignf(erf_y, x);
    float h = 0.5f * x;
    return fmaf(h, s, h);
}

__device__ __forceinline__ void mma16816(float (&c)[4],
    uint32_t a0, uint32_t a1, uint32_t a2, uint32_t a3, uint32_t b0, uint32_t b1) {
    asm volatile(
        "mma.sync.aligned.m16n8k16.row.col.f32.bf16.bf16.f32 "
        "{%0,%1,%2,%3}, {%4,%5,%6,%7}, {%8,%9}, {%0,%1,%2,%3};"
        : "+f"(c[0]), "+f"(c[1]), "+f"(c[2]), "+f"(c[3])
        : "r"(a0), "r"(a1), "r"(a2), "r"(a3), "r"(b0), "r"(b1));
}

// ---------- prep: zero scratch + transpose weights to bf16 ----------
__global__ void prep0_kernel(const float* __restrict__ vw1, const float* __restrict__ vw2) {
    int idx = blockIdx.x * blockDim.x + threadIdx.x;  // 16384 threads
    for (int o = idx; o < 32 * 2048; o += 16384) g_Sp[o] = 0.f;
    if (idx < 32 * 32) g_cntp[idx] = 0.f;
    if (idx < 8192) {
        g_w1t[idx] = __float2bfloat16(vw1[(idx & 63) * 128 + (idx >> 6)]);
        g_w2t[idx] = __float2bfloat16(vw2[(idx & 127) * 64 + (idx >> 7)]);
    }
}

// ---------- exact fp32 attention table ----------
__device__ __forceinline__ float blk_sum256(float v, float* sred, int t) {
    #pragma unroll
    for (int o = 16; o; o >>= 1) v += __shfl_xor_sync(0xffffffffu, v, o);
    __syncthreads();
    if ((t & 31) == 0) sred[t >> 5] = v;
    __syncthreads();
    float r = 0.f;
    #pragma unroll
    for (int w = 0; w < 8; w++) r += sred[w];
    return r;
}

__global__ void att_kernel(const float* __restrict__ qw1, const float* __restrict__ qb1,
                           const float* __restrict__ qg1, const float* __restrict__ qbt1,
                           const float* __restrict__ qw2, const float* __restrict__ qb2,
                           const float* __restrict__ qg2, const float* __restrict__ qbt2,
                           const float* __restrict__ qw3, const float* __restrict__ qb3,
                           const float* __restrict__ keys, const float* __restrict__ temperature) {
    __shared__ float sh[256], sq[256], sred[8], ssim[32];
    int t = threadIdx.x, idx = blockIdx.x;
    float v = 0.f;
    if (t < 128) {
        v = qb1[t];
        #pragma unroll
        for (int j = 0; j < 5; j++) v += (float)((idx >> j) & 1) * qw1[j * 128 + t];
    }
    float s1 = blk_sum256(v, sred, t);
    float s2 = blk_sum256(v * v, sred, t);
    if (t < 128) {
        float mean = s1 * (1.f / 128.f), var = s2 * (1.f / 128.f) - mean * mean;
        sh[t] = gelu_exact((v - mean) * rsqrtf(var + 1e-5f) * qg1[t] + qbt1[t]);
    }
    __syncthreads();
    float v2 = qb2[t];
    for (int k = 0; k < 128; k++) v2 += sh[k] * qw2[k * 256 + t];
    float s3 = blk_sum256(v2, sred, t);
    float s4 = blk_sum256(v2 * v2, sred, t);
    {
        float mean = s3 * (1.f / 256.f), var = s4 * (1.f / 256.f) - mean * mean;
        sh[t] = gelu_exact((v2 - mean) * rsqrtf(var + 1e-5f) * qg2[t] + qbt2[t]);
    }
    __syncthreads();
    float v3 = qb3[t];
    for (int k = 0; k < 256; k++) v3 += sh[k] * qw3[k * 256 + t];
    sq[t] = v3;
    float s5 = blk_sum256(v3 * v3, sred, t);
    float qnorm = fmaxf(sqrtf(s5), 1e-12f);
    int w = t >> 5, lane = t & 31;
    #pragma unroll
    for (int s = 0; s < 4; s++) {
        int n = w * 4 + s;
        float dot = 0.f, kn = 0.f;
        for (int d = lane; d < 256; d += 32) {
            float kv = keys[n * 256 + d];
            dot += sq[d] * kv; kn += kv * kv;
        }
        #pragma unroll
        for (int o = 16; o; o >>= 1) {
            dot += __shfl_xor_sync(0xffffffffu, dot, o);
            kn  += __shfl_xor_sync(0xffffffffu, kn, o);
        }
        if (lane == 0) ssim[n] = dot / (qnorm * fmaxf(sqrtf(kn), 1e-12f));
    }
    __syncthreads();
    if (t < 32) {
        float temp = fmaxf(fabsf(temperature[0]), 0.01f);
        float l = ssim[t] / temp, m = l;
        #pragma unroll
        for (int o = 16; o; o >>= 1) m = fmaxf(m, __shfl_xor_sync(0xffffffffu, m, o));
        float e = expf(l - m), ssum = e;
        #pragma unroll
        for (int o = 16; o; o >>= 1) ssum += __shfl_xor_sync(0xffffffffu, ssum, o);
        g_att[idx * 32 + t] = e / ssum;
    }
}

// ---------- enc: per-128-row tile, bf16 MMA MLP + one-hot scatter MMA ----------
#define ENC_SMEM_BYTES 56704
__global__ void __launch_bounds__(256) enc_kernel(
    const float* __restrict__ wval, const int* __restrict__ widx,
    const float* __restrict__ vb1, const float* __restrict__ vg1,
    const float* __restrict__ vbt1, const float* __restrict__ vb2) {
    extern __shared__ char smem[];
    uint32_t* sXu = (uint32_t*)(smem);                 // X bf16 [128][72] (stride 36 u32)
    __nv_bfloat16* sEt = (__nv_bfloat16*)(smem);       // reuse: E^T bf16 [64][136]
    uint32_t* sEtu = (uint32_t*)(smem);
    uint32_t* sW1u = (uint32_t*)(smem + 18432);        // W1^T [128][36 u32]
    uint32_t* sW2u = (uint32_t*)(smem + 36864);        // W2^T [64][68 u32]
    float* sSpart = (float*)(smem + 18432);            // reuse: [4][32][65] f32
    float* sVb1 = (float*)(smem + 54272);
    float* sVg1 = sVb1 + 128; float* sVbt1 = sVg1 + 128; float* sVb2 = sVbt1 + 128;
    int* sWidx = (int*)(smem + 56064);
    int* sCnt  = (int*)(smem + 56576);

    int tid = threadIdx.x, bid = blockIdx.x, rowbase = bid * 128;
    if (tid < 32) sCnt[tid] = 0;
    if (tid < 128) {
        sWidx[tid] = widx[rowbase + tid];
        sVb1[tid] = vb1[tid]; sVg1[tid] = vg1[tid]; sVbt1[tid] = vbt1[tid];
    }
    if (tid < 64) sVb2[tid] = vb2[tid];
    __syncthreads();
    if (tid < 128) atomicAdd(&sCnt[sWidx[tid]], 1);
    {
        const float2* wv2 = (const float2*)wval;
        #pragma unroll
        for (int rep = 0; rep < 16; rep++) {
            int o = rep * 256 + tid, r = o >> 5, cc = o & 31;
            float2 v = wv2[(size_t)(rowbase + r) * 32 + cc];
            if (sWidx[r] == 31) { v.x = 0.f; v.y = 0.f; }
            __nv_bfloat162 h = __floats2bfloat162_rn(v.x, v.y);
            uint32_t hu; memcpy(&hu, &h, 4);
            sXu[r * 36 + cc] = hu;
        }
        const uint32_t* w1 = (const uint32_t*)g_w1t;
        #pragma unroll
        for (int rep = 0; rep < 16; rep++) {
            int o = rep * 256 + tid;
            sW1u[(o >> 5) * 36 + (o & 31)] = w1[o];
        }
        const uint32_t* w2 = (const uint32_t*)g_w2t;
        #pragma unroll
        for (int rep = 0; rep < 16; rep++) {
            int o = rep * 256 + tid;
            sW2u[(o >> 6) * 68 + (o & 63)] = w2[o];
        }
    }
    __syncthreads();

    int w = tid >> 5, lane = tid & 31, g = lane >> 2, i = lane & 3;
    int r0 = w * 16 + g;

    // layer 1: X[128x64] @ W1[64x128]
    uint32_t A1[4][4];
    #pragma unroll
    for (int ks = 0; ks < 4; ks++) {
        int base = ks * 8 + i;
        A1[ks][0] = sXu[r0 * 36 + base];
        A1[ks][1] = sXu[(r0 + 8) * 36 + base];
        A1[ks][2] = sXu[r0 * 36 + base + 4];
        A1[ks][3] = sXu[(r0 + 8) * 36 + base + 4];
    }
    float C1[16][4];
    #pragma unroll
    for (int j = 0; j < 16; j++) C1[j][0] = C1[j][1] = C1[j][2] = C1[j][3] = 0.f;
    #pragma unroll
    for (int j = 0; j < 16; j++) {
        int nrow = j * 8 + g;
        #pragma unroll
        for (int ks = 0; ks < 4; ks++)
            mma16816(C1[j], A1[ks][0], A1[ks][1], A1[ks][2], A1[ks][3],
                     sW1u[nrow * 36 + ks * 8 + i], sW1u[nrow * 36 + ks * 8 + i + 4]);
    }
    // bias + LN stats + GELU, repack as layer-2 A fragments (in registers)
    #pragma unroll
    for (int j = 0; j < 16; j++) {
        float2 bb = *(float2*)&sVb1[j * 8 + i * 2];
        C1[j][0] += bb.x; C1[j][1] += bb.y; C1[j][2] += bb.x; C1[j][3] += bb.y;
    }
    float sum0 = 0.f, sq0 = 0.f, sum1 = 0.f, sq1 = 0.f;
    #pragma unroll
    for (int j = 0; j < 16; j++) {
        sum0 += C1[j][0] + C1[j][1]; sq0 += C1[j][0]*C1[j][0] + C1[j][1]*C1[j][1];
        sum1 += C1[j][2] + C1[j][3]; sq1 += C1[j][2]*C1[j][2] + C1[j][3]*C1[j][3];
    }
    #pragma unroll
    for (int o = 1; o <= 2; o <<= 1) {
        sum0 += __shfl_xor_sync(0xffffffffu, sum0, o);
        sq0  += __shfl_xor_sync(0xffffffffu, sq0, o);
        sum1 += __shfl_xor_sync(0xffffffffu, sum1, o);
        sq1  += __shfl_xor_sync(0xffffffffu, sq1, o);
    }
    float mean0 = sum0 * (1.f/128.f), var0 = sq0 * (1.f/128.f) - mean0*mean0;
    float mean1 = sum1 * (1.f/128.f), var1 = sq1 * (1.f/128.f) - mean1*mean1;
    float rs0 = rsqrtf(var0 + 1e-5f), rs1 = rsqrtf(var1 + 1e-5f);
    uint32_t A2[8][4];
    #pragma unroll
    for (int j = 0; j < 16; j++) {
        int c0 = j * 8 + i * 2;
        float2 gg = *(float2*)&sVg1[c0];
        float2 bb = *(float2*)&sVbt1[c0];
        float x0 = gelu_fast(fmaf((C1[j][0] - mean0) * rs0, gg.x, bb.x));
        float x1 = gelu_fast(fmaf((C1[j][1] - mean0) * rs0, gg.y, bb.y));
        float x2 = gelu_fast(fmaf((C1[j][2] - mean1) * rs1, gg.x, bb.x));
        float x3 = gelu_fast(fmaf((C1[j][3] - mean1) * rs1, gg.y, bb.y));
        __nv_bfloat162 p0 = __floats2bfloat162_rn(x0, x1);
        __nv_bfloat162 p1 = __floats2bfloat162_rn(x2, x3);
        uint32_t u0, u1; memcpy(&u0, &p0, 4); memcpy(&u1, &p1, 4);
        A2[j >> 1][(j & 1) * 2 + 0] = u0;
        A2[j >> 1][(j & 1) * 2 + 1] = u1;
    }
    // layer 2: H[128x128] @ W2[128x64]
    float C2[8][4];
    #pragma unroll
    for (int j = 0; j < 8; j++) C2[j][0] = C2[j][1] = C2[j][2] = C2[j][3] = 0.f;
    #pragma unroll
    for (int j = 0; j < 8; j++) {
        int nrow = j * 8 + g;
        #pragma unroll
        for (int ks = 0; ks < 8; ks++)
            mma16816(C2[j], A2[ks][0], A2[ks][1], A2[ks][2], A2[ks][3],
                     sW2u[nrow * 68 + ks * 8 + i], sW2u[nrow * 68 + ks * 8 + i + 4]);
    }
    #pragma unroll
    for (int j = 0; j < 8; j++) {
        float2 bb = *(float2*)&sVb2[j * 8 + i * 2];
        C2[j][0] += bb.x; C2[j][1] += bb.y; C2[j][2] += bb.x; C2[j][3] += bb.y;
    }
    __syncthreads();
    // store E^T bf16 [64][136], zero Spart
    #pragma unroll
    for (int j = 0; j < 8; j++) {
        int c0 = j * 8 + i * 2;
        sEt[(c0    ) * 136 + r0    ] = __float2bfloat16(C2[j][0]);
        sEt[(c0 + 1) * 136 + r0    ] = __float2bfloat16(C2[j][1]);
        sEt[(c0    ) * 136 + r0 + 8] = __float2bfloat16(C2[j][2]);
        sEt[(c0 + 1) * 136 + r0 + 8] = __float2bfloat16(C2[j][3]);
    }
    #pragma unroll
    for (int rep = 0; rep < 33; rep++) {
        int o = rep * 256 + tid;
        if (o < 4 * 32 * 65) sSpart[o] = 0.f;
    }
    __syncthreads();
    // S = Onehot(widx)^T (32x128) @ E (128x64); k-split across warp pairs
    int ksp = w >> 1, mh = w & 1;
    float CS[8][4];
    #pragma unroll
    for (int j = 0; j < 8; j++) CS[j][0] = CS[j][1] = CS[j][2] = CS[j][3] = 0.f;
    #pragma unroll
    for (int ks2 = 0; ks2 < 2; ks2++) {
        int kb = ksp * 32 + ks2 * 16, k0 = kb + i * 2;
        int x0 = sWidx[k0], x1 = sWidx[k0 + 1], x2 = sWidx[k0 + 8], x3 = sWidx[k0 + 9];
        int mlo = mh * 16 + g, mhi = mlo + 8;
        uint32_t a0 = (x0 == mlo ? 0x3F80u : 0u) | (x1 == mlo ? 0x3F800000u : 0u);
        uint32_t a1 = (x0 == mhi ? 0x3F80u : 0u) | (x1 == mhi ? 0x3F800000u : 0u);
        uint32_t a2 = (x2 == mlo ? 0x3F80u : 0u) | (x3 == mlo ? 0x3F800000u : 0u);
        uint32_t a3 = (x2 == mhi ? 0x3F80u : 0u) | (x3 == mhi ? 0x3F800000u : 0u);
        #pragma unroll
        for (int j = 0; j < 8; j++) {
            int nrow = j * 8 + g;
            mma16816(CS[j], a0, a1, a2, a3,
                     sEtu[nrow * 68 + (kb >> 1) + i], sEtu[nrow * 68 + (kb >> 1) + i + 4]);
        }
    }
    {
        float* p = &sSpart[ksp * 2080];
        int m0 = mh * 16 + g;
        #pragma unroll
        for (int j = 0; j < 8; j++) {
            int c0 = j * 8 + i * 2;
            p[m0 * 65 + c0]           = CS[j][0];
            p[m0 * 65 + c0 + 1]       = CS[j][1];
            p[(m0 + 8) * 65 + c0]     = CS[j][2];
            p[(m0 + 8) * 65 + c0 + 1] = CS[j][3];
        }
    }
    __syncthreads();
    int slice = bid & 31;
    #pragma unroll
    for (int rep = 0; rep < 8; rep++) {
        int o = rep * 256 + tid, m = o >> 6, c = o & 63;
        float v = sSpart[m * 65 + c] + sSpart[2080 + m * 65 + c]
                + sSpart[4160 + m * 65 + c] + sSpart[6240 + m * 65 + c];
        atomicAdd(&g_Sp[slice * 2048 + o], v);
    }
    if (tid < 32) atomicAdd(&g_cntp[slice * 32 + tid], (float)sCnt[tid]);
}

// ---------- parallel slice reduction ----------
__global__ void reduce_kernel() {
    int o = blockIdx.x * 256 + threadIdx.x;   // grid 8 x 256 = 2048
    float v = 0.f;
    #pragma unroll
    for (int sl = 0; sl < 32; sl++) v += g_Sp[sl * 2048 + o];
    g_S[o] = v;
    if (blockIdx.x == 0 && threadIdx.x < 32) {
        float c = 0.f;
        #pragma unroll
        for (int sl = 0; sl < 32; sl++) c += g_cntp[sl * 32 + threadIdx.x];
        g_cnt[threadIdx.x] = c;
    }
}

// ---------- finalize: new_regs + ROUT (slim) ----------
__global__ void finalize_kernel(const float* __restrict__ regvals,
                                const float* __restrict__ wstrength,
                                float* __restrict__ out, int Btot) {
    __shared__ float sS[2048], sATT[1024], sCnt[32], sM[32], sNR[2048];
    int t = threadIdx.x;  // 1024
    sATT[t] = g_att[t];
    sS[t] = g_S[t];
    sS[1024 + t] = g_S[1024 + t];
    if (t < 32) sCnt[t] = g_cnt[t];
    __syncthreads();
    float invB = 1.f / (float)Btot;
    if (t < 32) {
        float m = 0.f;
        for (int i2 = 0; i2 < 32; i2++) m += sCnt[i2] * invB * sATT[i2 * 32 + t];
        sM[t] = m;
    }
    __syncthreads();
    float s = 1.f / (1.f + expf(-wstrength[0]));
    #pragma unroll
    for (int rep = 0; rep < 2; rep++) {
        int o = rep * 1024 + t, n = o >> 6, d = o & 63;
        float as = 0.f;
        for (int i2 = 0; i2 < 32; i2++) as += sATT[i2 * 32 + n] * sS[i2 * 64 + d];
        float nr = (1.f - s * sM[n]) * regvals[o] + (s * invB) * as;
        out[(size_t)Btot * 64 + o] = nr;
        sNR[o] = nr;
    }
    __syncthreads();
    #pragma unroll
    for (int rep = 0; rep < 2; rep++) {
        int o = rep * 1024 + t, i2 = o >> 6, d = o & 63;
        float r = 0.f;
        for (int n = 0; n < 32; n++) r += sATT[i2 * 32 + n] * sNR[n * 64 + d];
        g_rout[o] = r;
    }
}

// ---------- read gather ----------
__global__ void __launch_bounds__(256) read_kernel(const int* __restrict__ ridx,
                                                   float* __restrict__ out) {
    __shared__ float4 sr[512];
    int t = threadIdx.x;
    #pragma unroll
    for (int rep = 0; rep < 2; rep++)
        sr[rep * 256 + t] = ((const float4*)g_rout)[rep * 256 + t];
    __syncthreads();
    int base = blockIdx.x * 128;
    #pragma unroll
    for (int it = 0; it < 8; it++) {
        int r = base + it * 16 + (t >> 4), cg = t & 15;
        int rv = ridx[r];
        float4 v = (rv == 31) ? make_float4(0.f, 0.f, 0.f, 0.f) : sr[rv * 16 + cg];
        ((float4*)out)[(size_t)r * 16 + cg] = v;
    }
}

// ---------- launcher ----------
extern "C" void kernel_launch(void* const* d_in, const int* in_sizes, int n_in,
                              void* d_out, int out_size) {
    const int*   wix  = (const int*)d_in[0];
    const float* wval = (const float*)d_in[1];
    const int*   rix  = (const int*)d_in[2];
    const float* regv = (const float*)d_in[3];
    const float* keys = (const float*)d_in[4];
    const float* qw1  = (const float*)d_in[5];
    const float* qb1  = (const float*)d_in[6];
    const float* qg1  = (const float*)d_in[7];
    const float* qbt1 = (const float*)d_in[8];
    const float* qw2  = (const float*)d_in[9];
    const float* qb2  = (const float*)d_in[10];
    const float* qg2  = (const float*)d_in[11];
    const float* qbt2 = (const float*)d_in[12];
    const float* qw3  = (const float*)d_in[13];
    const float* qb3  = (const float*)d_in[14];
    const float* vw1  = (const float*)d_in[15];
    const float* vb1  = (const float*)d_in[16];
    const float* vg1  = (const float*)d_in[17];
    const float* vbt1 = (const float*)d_in[18];
    const float* vw2  = (const float*)d_in[19];
    const float* vb2  = (const float*)d_in[20];
    const float* temp = (const float*)d_in[21];
    const float* wstr = (const float*)d_in[22];
    int B = in_sizes[0];

    cudaFuncSetAttribute(enc_kernel, cudaFuncAttributeMaxDynamicSharedMemorySize, ENC_SMEM_BYTES);

    prep0_kernel<<<64, 256>>>(vw1, vw2);
    att_kernel<<<32, 256>>>(qw1, qb1, qg1, qbt1, qw2, qb2, qg2, qbt2, qw3, qb3, keys, temp);
    enc_kernel<<<B / 128, 256, ENC_SMEM_BYTES>>>(wval, wix, vb1, vg1, vbt1, vb2);
    reduce_kernel<<<8, 256>>>();
    finalize_kernel<<<1, 1024>>>(regv, wstr, (float*)d_out, B);
    read_kernel<<<B / 128, 256>>>(rix, (float*)d_out);
}